// round 2
// baseline (speedup 1.0000x reference)
#include <cuda_runtime.h>
#include <cstdint>

#define D_DIM 1024
#define L_IN  1024
#define B_SZ  32
#define L_OUT 511
#define M_TOT (B_SZ * L_OUT)      /* 16352 */
#define K_CB  2048
#define K_C1  4096                /* D*4 */
#define BN_EPS 1e-5f
#define Q_ELEMS (B_SZ * D_DIM * L_OUT)  /* 16744448 */

/* ---------------- scratch (no cudaMalloc allowed) ---------------- */
__device__ float g_h [M_TOT * D_DIM];
__device__ float g_h2[M_TOT * D_DIM];
__device__ float g_part[2 * 64 * D_DIM];
__device__ float g_scale1[D_DIM], g_shift1[D_DIM];
__device__ float g_scale2[D_DIM], g_shift2[D_DIM];
__device__ float g_e2[K_CB];
__device__ unsigned long long g_keys[M_TOT];
__device__ double g_loss;

/* ---------------- init ---------------- */
__global__ void init_kernel() {
    int i = blockIdx.x * blockDim.x + threadIdx.x;
    if (i < M_TOT) g_keys[i] = 0xFFFFFFFFFFFFFFFFULL;
    if (i == 0) g_loss = 0.0;
}

/* ---------------- conv1: implicit GEMM  h[m][o] = X_patch[m][p] * W1[o][p] + b1[o] ----------------
 * m = b*511 + l,  p = i*4 + kk,  X_patch[m][p] = x[b, i, 2l+kk]
 */
__global__ void __launch_bounds__(256) conv1_kernel(const float* __restrict__ x,
                                                    const float* __restrict__ w1,
                                                    const float* __restrict__ b1) {
    __shared__ float As[16][68];
    __shared__ float Bs[16][68];
    __shared__ int   rowbase[64];

    int m0 = blockIdx.x * 64;
    int o0 = blockIdx.y * 64;
    int tid = threadIdx.x;
    int tx = tid & 15, ty = tid >> 4;

    if (tid < 64) {
        int m = m0 + tid; if (m >= M_TOT) m = M_TOT - 1;
        int b = m / L_OUT;
        int l = m - b * L_OUT;
        rowbase[tid] = b * (D_DIM * L_IN) + 2 * l;
    }
    __syncthreads();

    float acc[4][4] = {};

    for (int p0 = 0; p0 < K_C1; p0 += 16) {
#pragma unroll
        for (int r = 0; r < 4; r++) {          /* A: consecutive tid -> consecutive m */
            int idx = tid + r * 256;
            int pt = idx >> 6, mi = idx & 63;
            int p = p0 + pt;
            As[pt][mi] = x[rowbase[mi] + ((p >> 2) << 10) + (p & 3)];
        }
#pragma unroll
        for (int r = 0; r < 4; r++) {          /* B: consecutive tid -> consecutive p */
            int idx = tid + r * 256;
            int pt = idx & 15, oi = idx >> 4;
            Bs[pt][oi] = w1[(o0 + oi) * K_C1 + p0 + pt];
        }
        __syncthreads();
#pragma unroll
        for (int kk = 0; kk < 16; kk++) {
            float4 a4 = *(const float4*)&As[kk][ty * 4];
            float4 b4 = *(const float4*)&Bs[kk][tx * 4];
            float av[4] = {a4.x, a4.y, a4.z, a4.w};
            float bv[4] = {b4.x, b4.y, b4.z, b4.w};
#pragma unroll
            for (int i = 0; i < 4; i++)
#pragma unroll
                for (int j = 0; j < 4; j++) acc[i][j] += av[i] * bv[j];
        }
        __syncthreads();
    }

#pragma unroll
    for (int i = 0; i < 4; i++) {
        int m = m0 + ty * 4 + i;
        if (m < M_TOT) {
#pragma unroll
            for (int j = 0; j < 4; j++) {
                int o = o0 + tx * 4 + j;
                g_h[m * D_DIM + o] = acc[i][j] + b1[o];
            }
        }
    }
}

/* ---------------- BN stats: deterministic two-stage ---------------- */
__global__ void bn_stage1(int which) {
    const float* h = which ? g_h2 : g_h;
    int d = blockIdx.y * 128 + threadIdx.x;
    int s = blockIdx.x;                /* 64 slices of 256 m */
    float sum = 0.f, sq = 0.f;
    int mstart = s * 256;
    int mend = mstart + 256; if (mend > M_TOT) mend = M_TOT;
    for (int m = mstart; m < mend; m++) {
        float v = h[m * D_DIM + d];
        sum += v; sq += v * v;
    }
    g_part[s * D_DIM + d] = sum;
    g_part[64 * D_DIM + s * D_DIM + d] = sq;
}

__global__ void bn_stage2(const float* __restrict__ gam, const float* __restrict__ bet, int which) {
    int d = blockIdx.x * 256 + threadIdx.x;
    float sum = 0.f, sq = 0.f;
    for (int s = 0; s < 64; s++) {
        sum += g_part[s * D_DIM + d];
        sq  += g_part[64 * D_DIM + s * D_DIM + d];
    }
    float mean = sum / (float)M_TOT;
    float var  = sq / (float)M_TOT - mean * mean;
    float sc = gam[d] * rsqrtf(var + BN_EPS);
    float sh = bet[d] - mean * sc;
    if (which == 0) { g_scale1[d] = sc; g_shift1[d] = sh; }
    else            { g_scale2[d] = sc; g_shift2[d] = sh; }
}

/* ---------------- conv2 1x1 + residual: h2 = h + relu(bn1(h)) @ W2^T + b2 ---------------- */
__global__ void __launch_bounds__(256) conv2_kernel(const float* __restrict__ w2,
                                                    const float* __restrict__ b2) {
    __shared__ float As[16][68];
    __shared__ float Bs[16][68];
    int m0 = blockIdx.x * 64;
    int o0 = blockIdx.y * 64;
    int tid = threadIdx.x;
    int tx = tid & 15, ty = tid >> 4;
    float acc[4][4] = {};

    for (int p0 = 0; p0 < D_DIM; p0 += 16) {
#pragma unroll
        for (int r = 0; r < 4; r++) {
            int idx = tid + r * 256;
            int pt = idx & 15, mi = idx >> 4;
            int m = m0 + mi; if (m >= M_TOT) m = M_TOT - 1;
            int p = p0 + pt;
            float v = g_h[m * D_DIM + p] * g_scale1[p] + g_shift1[p];
            As[pt][mi] = fmaxf(v, 0.f);
        }
#pragma unroll
        for (int r = 0; r < 4; r++) {
            int idx = tid + r * 256;
            int pt = idx & 15, oi = idx >> 4;
            Bs[pt][oi] = w2[(o0 + oi) * D_DIM + p0 + pt];
        }
        __syncthreads();
#pragma unroll
        for (int kk = 0; kk < 16; kk++) {
            float4 a4 = *(const float4*)&As[kk][ty * 4];
            float4 b4 = *(const float4*)&Bs[kk][tx * 4];
            float av[4] = {a4.x, a4.y, a4.z, a4.w};
            float bv[4] = {b4.x, b4.y, b4.z, b4.w};
#pragma unroll
            for (int i = 0; i < 4; i++)
#pragma unroll
                for (int j = 0; j < 4; j++) acc[i][j] += av[i] * bv[j];
        }
        __syncthreads();
    }

#pragma unroll
    for (int i = 0; i < 4; i++) {
        int m = m0 + ty * 4 + i;
        if (m < M_TOT) {
#pragma unroll
            for (int j = 0; j < 4; j++) {
                int o = o0 + tx * 4 + j;
                g_h2[m * D_DIM + o] = g_h[m * D_DIM + o] + acc[i][j] + b2[o];
            }
        }
    }
}

/* ---------------- codebook squared norms ---------------- */
__global__ void e2_kernel(const float* __restrict__ cb) {
    int k = blockIdx.x;
    float s = 0.f;
    for (int d = threadIdx.x; d < D_DIM; d += 128) {
        float v = cb[k * D_DIM + d];
        s += v * v;
    }
    __shared__ float red[128];
    red[threadIdx.x] = s;
    __syncthreads();
    for (int off = 64; off; off >>= 1) {
        if (threadIdx.x < off) red[threadIdx.x] += red[threadIdx.x + off];
        __syncthreads();
    }
    if (threadIdx.x == 0) g_e2[k] = red[0];
}

/* ---------------- VQ: score[m][k] = e2[k] - 2 * z[m].e[k];  argmin via packed atomicMin ---------- */
__global__ void __launch_bounds__(256) vq_kernel(const float* __restrict__ cb) {
    __shared__ float As[16][68];
    __shared__ float Bs[16][68];
    int m0 = blockIdx.x * 64;
    int kbase0 = blockIdx.y * 512;
    int tid = threadIdx.x;
    int tx = tid & 15, ty = tid >> 4;

    float best[4] = {3.4e38f, 3.4e38f, 3.4e38f, 3.4e38f};
    int bestk[4] = {0, 0, 0, 0};

    for (int kt = 0; kt < 8; kt++) {
        int k0 = kbase0 + kt * 64;
        float acc[4][4] = {};
        for (int p0 = 0; p0 < D_DIM; p0 += 16) {
#pragma unroll
            for (int r = 0; r < 4; r++) {
                int idx = tid + r * 256;
                int pt = idx & 15, mi = idx >> 4;
                int m = m0 + mi; if (m >= M_TOT) m = M_TOT - 1;
                int p = p0 + pt;
                As[pt][mi] = g_h2[m * D_DIM + p] * g_scale2[p] + g_shift2[p];
            }
#pragma unroll
            for (int r = 0; r < 4; r++) {
                int idx = tid + r * 256;
                int pt = idx & 15, ki = idx >> 4;
                Bs[pt][ki] = cb[(k0 + ki) * D_DIM + p0 + pt];
            }
            __syncthreads();
#pragma unroll
            for (int kk = 0; kk < 16; kk++) {
                float4 a4 = *(const float4*)&As[kk][ty * 4];
                float4 b4 = *(const float4*)&Bs[kk][tx * 4];
                float av[4] = {a4.x, a4.y, a4.z, a4.w};
                float bv[4] = {b4.x, b4.y, b4.z, b4.w};
#pragma unroll
                for (int i = 0; i < 4; i++)
#pragma unroll
                    for (int j = 0; j < 4; j++) acc[i][j] += av[i] * bv[j];
            }
            __syncthreads();
        }
#pragma unroll
        for (int i = 0; i < 4; i++) {
#pragma unroll
            for (int j = 0; j < 4; j++) {
                int k = k0 + tx * 4 + j;
                float score = g_e2[k] - 2.f * acc[i][j];
                if (score < best[i]) { best[i] = score; bestk[i] = k; }
            }
        }
    }

    /* per-m reduction across the 16 tx lanes, then global atomicMin */
    __shared__ unsigned long long kred[64][17];
#pragma unroll
    for (int i = 0; i < 4; i++) {
        unsigned u = __float_as_uint(best[i]);
        u = (u & 0x80000000u) ? ~u : (u | 0x80000000u);   /* order-preserving */
        kred[ty * 4 + i][tx] = ((unsigned long long)u << 32) | (unsigned)bestk[i];
    }
    __syncthreads();
    if (tid < 64) {
        unsigned long long mn = kred[tid][0];
#pragma unroll
        for (int t = 1; t < 16; t++) {
            unsigned long long v = kred[tid][t];
            if (v < mn) mn = v;
        }
        int m = m0 + tid;
        if (m < M_TOT) atomicMin(&g_keys[m], mn);
    }
}

/* ---------------- gather q = codebook[id], write [B,D,L'], ids, and loss ---------------- */
__global__ void gather_kernel(const float* __restrict__ cb, float* __restrict__ out) {
    int b = blockIdx.y;
    int l = blockIdx.x * 32 + threadIdx.x;
    int dt = threadIdx.y;          /* 0..7 */
    float local = 0.f;
    if (l < L_OUT) {
        int m = b * L_OUT + l;
        int id = (int)(unsigned)(g_keys[m] & 0xFFFFFFFFULL);
        if (dt == 0) out[Q_ELEMS + m] = (float)id;
        for (int d = dt; d < D_DIM; d += 8) {
            float q = cb[id * D_DIM + d];
            float z = g_h2[m * D_DIM + d] * g_scale2[d] + g_shift2[d];
            out[b * (D_DIM * L_OUT) + d * L_OUT + l] = q;
            float diff = z - q;
            local += diff * diff;
        }
    }
    __shared__ double red[256];
    int t = threadIdx.y * 32 + threadIdx.x;
    red[t] = (double)local;
    __syncthreads();
    for (int off = 128; off; off >>= 1) {
        if (t < off) red[t] += red[t + off];
        __syncthreads();
    }
    if (t == 0) atomicAdd(&g_loss, red[0]);
}

__global__ void finalize_kernel(float* __restrict__ out) {
    if (threadIdx.x == 0 && blockIdx.x == 0) {
        float loss = (float)(g_loss / (double)Q_ELEMS);
        out[Q_ELEMS + M_TOT]     = loss;   /* commitment  */
        out[Q_ELEMS + M_TOT + 1] = loss;   /* codebook_loss (identical) */
    }
}

/* ---------------- launch ---------------- */
extern "C" void kernel_launch(void* const* d_in, const int* in_sizes, int n_in,
                              void* d_out, int out_size) {
    const float* x   = (const float*)d_in[0];
    const float* w1  = (const float*)d_in[1];
    const float* b1  = (const float*)d_in[2];
    const float* g1  = (const float*)d_in[3];
    const float* be1 = (const float*)d_in[4];
    const float* w2  = (const float*)d_in[5];
    const float* b2  = (const float*)d_in[6];
    const float* g2  = (const float*)d_in[7];
    const float* be2 = (const float*)d_in[8];
    const float* cb  = (const float*)d_in[9];
    float* out = (float*)d_out;

    init_kernel<<<64, 256>>>();
    conv1_kernel<<<dim3(256, 16), 256>>>(x, w1, b1);
    bn_stage1<<<dim3(64, 8), 128>>>(0);
    bn_stage2<<<4, 256>>>(g1, be1, 0);
    conv2_kernel<<<dim3(256, 16), 256>>>(w2, b2);
    bn_stage1<<<dim3(64, 8), 128>>>(1);
    bn_stage2<<<4, 256>>>(g2, be2, 1);
    e2_kernel<<<K_CB, 128>>>(cb);
    vq_kernel<<<dim3(256, 4), 256>>>(cb);
    gather_kernel<<<dim3(16, B_SZ), dim3(32, 8)>>>(cb, out);
    finalize_kernel<<<1, 32>>>(out);
}

// round 3
// speedup vs baseline: 1.0015x; 1.0015x over previous
#include <cuda_runtime.h>
#include <cstdint>

#define D_DIM 1024
#define L_IN  1024
#define B_SZ  32
#define L_OUT 511
#define M_TOT (B_SZ * L_OUT)      /* 16352 */
#define K_CB  2048
#define K_C1  4096                /* D*4 */
#define BN_EPS 1e-5f
#define Q_ELEMS (B_SZ * D_DIM * L_OUT)  /* 16744448 */

/* ---------------- scratch (no cudaMalloc allowed) ---------------- */
__device__ float g_h [M_TOT * D_DIM];
__device__ float g_h2[M_TOT * D_DIM];
__device__ float g_part[2 * 64 * D_DIM];
__device__ float g_scale1[D_DIM], g_shift1[D_DIM];
__device__ float g_scale2[D_DIM], g_shift2[D_DIM];
__device__ float g_e2[K_CB];
__device__ unsigned long long g_keys[M_TOT];
__device__ double g_loss;

/* ---------------- init ---------------- */
__global__ void init_kernel() {
    int i = blockIdx.x * blockDim.x + threadIdx.x;
    if (i < M_TOT) g_keys[i] = 0xFFFFFFFFFFFFFFFFULL;
    if (i == 0) g_loss = 0.0;
}

/* ---------------- conv1: implicit GEMM  h[m][o] = X_patch[m][p] * W1[o][p] + b1[o] ----------------
 * m = b*511 + l,  p = i*4 + kk,  X_patch[m][p] = x[b, i, 2l+kk]
 */
__global__ void __launch_bounds__(256) conv1_kernel(const float* __restrict__ x,
                                                    const float* __restrict__ w1,
                                                    const float* __restrict__ b1) {
    __shared__ float As[16][68];
    __shared__ float Bs[16][68];
    __shared__ int   rowbase[64];

    int m0 = blockIdx.x * 64;
    int o0 = blockIdx.y * 64;
    int tid = threadIdx.x;
    int tx = tid & 15, ty = tid >> 4;

    if (tid < 64) {
        int m = m0 + tid; if (m >= M_TOT) m = M_TOT - 1;
        int b = m / L_OUT;
        int l = m - b * L_OUT;
        rowbase[tid] = b * (D_DIM * L_IN) + 2 * l;
    }
    __syncthreads();

    float acc[4][4] = {};

    for (int p0 = 0; p0 < K_C1; p0 += 16) {
#pragma unroll
        for (int r = 0; r < 4; r++) {          /* A: consecutive tid -> consecutive m */
            int idx = tid + r * 256;
            int pt = idx >> 6, mi = idx & 63;
            int p = p0 + pt;
            As[pt][mi] = x[rowbase[mi] + ((p >> 2) << 10) + (p & 3)];
        }
#pragma unroll
        for (int r = 0; r < 4; r++) {          /* B: consecutive tid -> consecutive p */
            int idx = tid + r * 256;
            int pt = idx & 15, oi = idx >> 4;
            Bs[pt][oi] = w1[(o0 + oi) * K_C1 + p0 + pt];
        }
        __syncthreads();
#pragma unroll
        for (int kk = 0; kk < 16; kk++) {
            float4 a4 = *(const float4*)&As[kk][ty * 4];
            float4 b4 = *(const float4*)&Bs[kk][tx * 4];
            float av[4] = {a4.x, a4.y, a4.z, a4.w};
            float bv[4] = {b4.x, b4.y, b4.z, b4.w};
#pragma unroll
            for (int i = 0; i < 4; i++)
#pragma unroll
                for (int j = 0; j < 4; j++) acc[i][j] += av[i] * bv[j];
        }
        __syncthreads();
    }

#pragma unroll
    for (int i = 0; i < 4; i++) {
        int m = m0 + ty * 4 + i;
        if (m < M_TOT) {
#pragma unroll
            for (int j = 0; j < 4; j++) {
                int o = o0 + tx * 4 + j;
                g_h[m * D_DIM + o] = acc[i][j] + b1[o];
            }
        }
    }
}

/* ---------------- BN stats: deterministic two-stage ---------------- */
__global__ void bn_stage1(int which) {
    const float* h = which ? g_h2 : g_h;
    int d = blockIdx.y * 128 + threadIdx.x;
    int s = blockIdx.x;                /* 64 slices of 256 m */
    float sum = 0.f, sq = 0.f;
    int mstart = s * 256;
    int mend = mstart + 256; if (mend > M_TOT) mend = M_TOT;
    for (int m = mstart; m < mend; m++) {
        float v = h[m * D_DIM + d];
        sum += v; sq += v * v;
    }
    g_part[s * D_DIM + d] = sum;
    g_part[64 * D_DIM + s * D_DIM + d] = sq;
}

__global__ void bn_stage2(const float* __restrict__ gam, const float* __restrict__ bet, int which) {
    int d = blockIdx.x * 256 + threadIdx.x;
    float sum = 0.f, sq = 0.f;
    for (int s = 0; s < 64; s++) {
        sum += g_part[s * D_DIM + d];
        sq  += g_part[64 * D_DIM + s * D_DIM + d];
    }
    float mean = sum / (float)M_TOT;
    float var  = sq / (float)M_TOT - mean * mean;
    float sc = gam[d] * rsqrtf(var + BN_EPS);
    float sh = bet[d] - mean * sc;
    if (which == 0) { g_scale1[d] = sc; g_shift1[d] = sh; }
    else            { g_scale2[d] = sc; g_shift2[d] = sh; }
}

/* ---------------- conv2 1x1 + residual: h2 = h + relu(bn1(h)) @ W2^T + b2 ---------------- */
__global__ void __launch_bounds__(256) conv2_kernel(const float* __restrict__ w2,
                                                    const float* __restrict__ b2) {
    __shared__ float As[16][68];
    __shared__ float Bs[16][68];
    int m0 = blockIdx.x * 64;
    int o0 = blockIdx.y * 64;
    int tid = threadIdx.x;
    int tx = tid & 15, ty = tid >> 4;
    float acc[4][4] = {};

    for (int p0 = 0; p0 < D_DIM; p0 += 16) {
#pragma unroll
        for (int r = 0; r < 4; r++) {
            int idx = tid + r * 256;
            int pt = idx & 15, mi = idx >> 4;
            int m = m0 + mi; if (m >= M_TOT) m = M_TOT - 1;
            int p = p0 + pt;
            float v = g_h[m * D_DIM + p] * g_scale1[p] + g_shift1[p];
            As[pt][mi] = fmaxf(v, 0.f);
        }
#pragma unroll
        for (int r = 0; r < 4; r++) {
            int idx = tid + r * 256;
            int pt = idx & 15, oi = idx >> 4;
            Bs[pt][oi] = w2[(o0 + oi) * D_DIM + p0 + pt];
        }
        __syncthreads();
#pragma unroll
        for (int kk = 0; kk < 16; kk++) {
            float4 a4 = *(const float4*)&As[kk][ty * 4];
            float4 b4 = *(const float4*)&Bs[kk][tx * 4];
            float av[4] = {a4.x, a4.y, a4.z, a4.w};
            float bv[4] = {b4.x, b4.y, b4.z, b4.w};
#pragma unroll
            for (int i = 0; i < 4; i++)
#pragma unroll
                for (int j = 0; j < 4; j++) acc[i][j] += av[i] * bv[j];
        }
        __syncthreads();
    }

#pragma unroll
    for (int i = 0; i < 4; i++) {
        int m = m0 + ty * 4 + i;
        if (m < M_TOT) {
#pragma unroll
            for (int j = 0; j < 4; j++) {
                int o = o0 + tx * 4 + j;
                g_h2[m * D_DIM + o] = g_h[m * D_DIM + o] + acc[i][j] + b2[o];
            }
        }
    }
}

/* ---------------- codebook squared norms ---------------- */
__global__ void e2_kernel(const float* __restrict__ cb) {
    int k = blockIdx.x;
    float s = 0.f;
    for (int d = threadIdx.x; d < D_DIM; d += 128) {
        float v = cb[k * D_DIM + d];
        s += v * v;
    }
    __shared__ float red[128];
    red[threadIdx.x] = s;
    __syncthreads();
    for (int off = 64; off; off >>= 1) {
        if (threadIdx.x < off) red[threadIdx.x] += red[threadIdx.x + off];
        __syncthreads();
    }
    if (threadIdx.x == 0) g_e2[k] = red[0];
}

/* ---------------- VQ: score[m][k] = e2[k] - 2 * z[m].e[k];  argmin via packed atomicMin ---------- */
__global__ void __launch_bounds__(256) vq_kernel(const float* __restrict__ cb) {
    __shared__ float As[16][68];
    __shared__ float Bs[16][68];
    int m0 = blockIdx.x * 64;
    int kbase0 = blockIdx.y * 512;
    int tid = threadIdx.x;
    int tx = tid & 15, ty = tid >> 4;

    float best[4] = {3.4e38f, 3.4e38f, 3.4e38f, 3.4e38f};
    int bestk[4] = {0, 0, 0, 0};

    for (int kt = 0; kt < 8; kt++) {
        int k0 = kbase0 + kt * 64;
        float acc[4][4] = {};
        for (int p0 = 0; p0 < D_DIM; p0 += 16) {
#pragma unroll
            for (int r = 0; r < 4; r++) {
                int idx = tid + r * 256;
                int pt = idx & 15, mi = idx >> 4;
                int m = m0 + mi; if (m >= M_TOT) m = M_TOT - 1;
                int p = p0 + pt;
                As[pt][mi] = g_h2[m * D_DIM + p] * g_scale2[p] + g_shift2[p];
            }
#pragma unroll
            for (int r = 0; r < 4; r++) {
                int idx = tid + r * 256;
                int pt = idx & 15, ki = idx >> 4;
                Bs[pt][ki] = cb[(k0 + ki) * D_DIM + p0 + pt];
            }
            __syncthreads();
#pragma unroll
            for (int kk = 0; kk < 16; kk++) {
                float4 a4 = *(const float4*)&As[kk][ty * 4];
                float4 b4 = *(const float4*)&Bs[kk][tx * 4];
                float av[4] = {a4.x, a4.y, a4.z, a4.w};
                float bv[4] = {b4.x, b4.y, b4.z, b4.w};
#pragma unroll
                for (int i = 0; i < 4; i++)
#pragma unroll
                    for (int j = 0; j < 4; j++) acc[i][j] += av[i] * bv[j];
            }
            __syncthreads();
        }
#pragma unroll
        for (int i = 0; i < 4; i++) {
#pragma unroll
            for (int j = 0; j < 4; j++) {
                int k = k0 + tx * 4 + j;
                float score = g_e2[k] - 2.f * acc[i][j];
                if (score < best[i]) { best[i] = score; bestk[i] = k; }
            }
        }
    }

    /* per-m reduction across the 16 tx lanes, then global atomicMin */
    __shared__ unsigned long long kred[64][17];
#pragma unroll
    for (int i = 0; i < 4; i++) {
        unsigned u = __float_as_uint(best[i]);
        u = (u & 0x80000000u) ? ~u : (u | 0x80000000u);   /* order-preserving */
        kred[ty * 4 + i][tx] = ((unsigned long long)u << 32) | (unsigned)bestk[i];
    }
    __syncthreads();
    if (tid < 64) {
        unsigned long long mn = kred[tid][0];
#pragma unroll
        for (int t = 1; t < 16; t++) {
            unsigned long long v = kred[tid][t];
            if (v < mn) mn = v;
        }
        int m = m0 + tid;
        if (m < M_TOT) atomicMin(&g_keys[m], mn);
    }
}

/* ---------------- gather q = codebook[id], write [B,D,L'], ids, and loss ---------------- */
__global__ void gather_kernel(const float* __restrict__ cb, float* __restrict__ out) {
    int b = blockIdx.y;
    int l = blockIdx.x * 32 + threadIdx.x;
    int dt = threadIdx.y;          /* 0..7 */
    float local = 0.f;
    if (l < L_OUT) {
        int m = b * L_OUT + l;
        int id = (int)(unsigned)(g_keys[m] & 0xFFFFFFFFULL);
        if (dt == 0) out[Q_ELEMS + m] = (float)id;
        for (int d = dt; d < D_DIM; d += 8) {
            float q = cb[id * D_DIM + d];
            float z = g_h2[m * D_DIM + d] * g_scale2[d] + g_shift2[d];
            out[b * (D_DIM * L_OUT) + d * L_OUT + l] = q;
            float diff = z - q;
            local += diff * diff;
        }
    }
    __shared__ double red[256];
    int t = threadIdx.y * 32 + threadIdx.x;
    red[t] = (double)local;
    __syncthreads();
    for (int off = 128; off; off >>= 1) {
        if (t < off) red[t] += red[t + off];
        __syncthreads();
    }
    if (t == 0) atomicAdd(&g_loss, red[0]);
}

__global__ void finalize_kernel(float* __restrict__ out) {
    if (threadIdx.x == 0 && blockIdx.x == 0) {
        float loss = (float)(g_loss / (double)Q_ELEMS);
        out[Q_ELEMS + M_TOT]     = loss;   /* commitment  */
        out[Q_ELEMS + M_TOT + 1] = loss;   /* codebook_loss (identical) */
    }
}

/* ---------------- launch ---------------- */
extern "C" void kernel_launch(void* const* d_in, const int* in_sizes, int n_in,
                              void* d_out, int out_size) {
    const float* x   = (const float*)d_in[0];
    const float* w1  = (const float*)d_in[1];
    const float* b1  = (const float*)d_in[2];
    const float* g1  = (const float*)d_in[3];
    const float* be1 = (const float*)d_in[4];
    const float* w2  = (const float*)d_in[5];
    const float* b2  = (const float*)d_in[6];
    const float* g2  = (const float*)d_in[7];
    const float* be2 = (const float*)d_in[8];
    const float* cb  = (const float*)d_in[9];
    float* out = (float*)d_out;

    init_kernel<<<64, 256>>>();
    conv1_kernel<<<dim3(256, 16), 256>>>(x, w1, b1);
    bn_stage1<<<dim3(64, 8), 128>>>(0);
    bn_stage2<<<4, 256>>>(g1, be1, 0);
    conv2_kernel<<<dim3(256, 16), 256>>>(w2, b2);
    bn_stage1<<<dim3(64, 8), 128>>>(1);
    bn_stage2<<<4, 256>>>(g2, be2, 1);
    e2_kernel<<<K_CB, 128>>>(cb);
    vq_kernel<<<dim3(256, 4), 256>>>(cb);
    gather_kernel<<<dim3(16, B_SZ), dim3(32, 8)>>>(cb, out);
    finalize_kernel<<<1, 32>>>(out);
}

// round 4
// speedup vs baseline: 1.0023x; 1.0008x over previous
#include <cuda_runtime.h>
#include <cstdint>

#define D_DIM 1024
#define L_IN  1024
#define B_SZ  32
#define L_OUT 511
#define M_TOT (B_SZ * L_OUT)      /* 16352 */
#define K_CB  2048
#define K_C1  4096                /* D*4 */
#define BN_EPS 1e-5f
#define Q_ELEMS (B_SZ * D_DIM * L_OUT)  /* 16744448 */

/* ---------------- scratch (no cudaMalloc allowed) ---------------- */
__device__ float g_h [M_TOT * D_DIM];
__device__ float g_h2[M_TOT * D_DIM];
__device__ float g_part[2 * 64 * D_DIM];
__device__ float g_scale1[D_DIM], g_shift1[D_DIM];
__device__ float g_scale2[D_DIM], g_shift2[D_DIM];
__device__ float g_e2[K_CB];
__device__ unsigned long long g_keys[M_TOT];
__device__ double g_loss;

/* ---------------- init ---------------- */
__global__ void init_kernel() {
    int i = blockIdx.x * blockDim.x + threadIdx.x;
    if (i < M_TOT) g_keys[i] = 0xFFFFFFFFFFFFFFFFULL;
    if (i == 0) g_loss = 0.0;
}

/* ---------------- conv1: implicit GEMM  h[m][o] = X_patch[m][p] * W1[o][p] + b1[o] ----------------
 * m = b*511 + l,  p = i*4 + kk,  X_patch[m][p] = x[b, i, 2l+kk]
 */
__global__ void __launch_bounds__(256) conv1_kernel(const float* __restrict__ x,
                                                    const float* __restrict__ w1,
                                                    const float* __restrict__ b1) {
    __shared__ float As[16][68];
    __shared__ float Bs[16][68];
    __shared__ int   rowbase[64];

    int m0 = blockIdx.x * 64;
    int o0 = blockIdx.y * 64;
    int tid = threadIdx.x;
    int tx = tid & 15, ty = tid >> 4;

    if (tid < 64) {
        int m = m0 + tid; if (m >= M_TOT) m = M_TOT - 1;
        int b = m / L_OUT;
        int l = m - b * L_OUT;
        rowbase[tid] = b * (D_DIM * L_IN) + 2 * l;
    }
    __syncthreads();

    float acc[4][4] = {};

    for (int p0 = 0; p0 < K_C1; p0 += 16) {
#pragma unroll
        for (int r = 0; r < 4; r++) {          /* A: consecutive tid -> consecutive m */
            int idx = tid + r * 256;
            int pt = idx >> 6, mi = idx & 63;
            int p = p0 + pt;
            As[pt][mi] = x[rowbase[mi] + ((p >> 2) << 10) + (p & 3)];
        }
#pragma unroll
        for (int r = 0; r < 4; r++) {          /* B: consecutive tid -> consecutive p */
            int idx = tid + r * 256;
            int pt = idx & 15, oi = idx >> 4;
            Bs[pt][oi] = w1[(o0 + oi) * K_C1 + p0 + pt];
        }
        __syncthreads();
#pragma unroll
        for (int kk = 0; kk < 16; kk++) {
            float4 a4 = *(const float4*)&As[kk][ty * 4];
            float4 b4 = *(const float4*)&Bs[kk][tx * 4];
            float av[4] = {a4.x, a4.y, a4.z, a4.w};
            float bv[4] = {b4.x, b4.y, b4.z, b4.w};
#pragma unroll
            for (int i = 0; i < 4; i++)
#pragma unroll
                for (int j = 0; j < 4; j++) acc[i][j] += av[i] * bv[j];
        }
        __syncthreads();
    }

#pragma unroll
    for (int i = 0; i < 4; i++) {
        int m = m0 + ty * 4 + i;
        if (m < M_TOT) {
#pragma unroll
            for (int j = 0; j < 4; j++) {
                int o = o0 + tx * 4 + j;
                g_h[m * D_DIM + o] = acc[i][j] + b1[o];
            }
        }
    }
}

/* ---------------- BN stats: deterministic two-stage ---------------- */
__global__ void bn_stage1(int which) {
    const float* h = which ? g_h2 : g_h;
    int d = blockIdx.y * 128 + threadIdx.x;
    int s = blockIdx.x;                /* 64 slices of 256 m */
    float sum = 0.f, sq = 0.f;
    int mstart = s * 256;
    int mend = mstart + 256; if (mend > M_TOT) mend = M_TOT;
    for (int m = mstart; m < mend; m++) {
        float v = h[m * D_DIM + d];
        sum += v; sq += v * v;
    }
    g_part[s * D_DIM + d] = sum;
    g_part[64 * D_DIM + s * D_DIM + d] = sq;
}

__global__ void bn_stage2(const float* __restrict__ gam, const float* __restrict__ bet, int which) {
    int d = blockIdx.x * 256 + threadIdx.x;
    float sum = 0.f, sq = 0.f;
    for (int s = 0; s < 64; s++) {
        sum += g_part[s * D_DIM + d];
        sq  += g_part[64 * D_DIM + s * D_DIM + d];
    }
    float mean = sum / (float)M_TOT;
    float var  = sq / (float)M_TOT - mean * mean;
    float sc = gam[d] * rsqrtf(var + BN_EPS);
    float sh = bet[d] - mean * sc;
    if (which == 0) { g_scale1[d] = sc; g_shift1[d] = sh; }
    else            { g_scale2[d] = sc; g_shift2[d] = sh; }
}

/* ---------------- conv2 1x1 + residual: h2 = h + relu(bn1(h)) @ W2^T + b2 ---------------- */
__global__ void __launch_bounds__(256) conv2_kernel(const float* __restrict__ w2,
                                                    const float* __restrict__ b2) {
    __shared__ float As[16][68];
    __shared__ float Bs[16][68];
    int m0 = blockIdx.x * 64;
    int o0 = blockIdx.y * 64;
    int tid = threadIdx.x;
    int tx = tid & 15, ty = tid >> 4;
    float acc[4][4] = {};

    for (int p0 = 0; p0 < D_DIM; p0 += 16) {
#pragma unroll
        for (int r = 0; r < 4; r++) {
            int idx = tid + r * 256;
            int pt = idx & 15, mi = idx >> 4;
            int m = m0 + mi; if (m >= M_TOT) m = M_TOT - 1;
            int p = p0 + pt;
            float v = g_h[m * D_DIM + p] * g_scale1[p] + g_shift1[p];
            As[pt][mi] = fmaxf(v, 0.f);
        }
#pragma unroll
        for (int r = 0; r < 4; r++) {
            int idx = tid + r * 256;
            int pt = idx & 15, oi = idx >> 4;
            Bs[pt][oi] = w2[(o0 + oi) * D_DIM + p0 + pt];
        }
        __syncthreads();
#pragma unroll
        for (int kk = 0; kk < 16; kk++) {
            float4 a4 = *(const float4*)&As[kk][ty * 4];
            float4 b4 = *(const float4*)&Bs[kk][tx * 4];
            float av[4] = {a4.x, a4.y, a4.z, a4.w};
            float bv[4] = {b4.x, b4.y, b4.z, b4.w};
#pragma unroll
            for (int i = 0; i < 4; i++)
#pragma unroll
                for (int j = 0; j < 4; j++) acc[i][j] += av[i] * bv[j];
        }
        __syncthreads();
    }

#pragma unroll
    for (int i = 0; i < 4; i++) {
        int m = m0 + ty * 4 + i;
        if (m < M_TOT) {
#pragma unroll
            for (int j = 0; j < 4; j++) {
                int o = o0 + tx * 4 + j;
                g_h2[m * D_DIM + o] = g_h[m * D_DIM + o] + acc[i][j] + b2[o];
            }
        }
    }
}

/* ---------------- codebook squared norms ---------------- */
__global__ void e2_kernel(const float* __restrict__ cb) {
    int k = blockIdx.x;
    float s = 0.f;
    for (int d = threadIdx.x; d < D_DIM; d += 128) {
        float v = cb[k * D_DIM + d];
        s += v * v;
    }
    __shared__ float red[128];
    red[threadIdx.x] = s;
    __syncthreads();
    for (int off = 64; off; off >>= 1) {
        if (threadIdx.x < off) red[threadIdx.x] += red[threadIdx.x + off];
        __syncthreads();
    }
    if (threadIdx.x == 0) g_e2[k] = red[0];
}

/* ---------------- VQ: score[m][k] = e2[k] - 2 * z[m].e[k];  argmin via packed atomicMin ---------- */
__global__ void __launch_bounds__(256) vq_kernel(const float* __restrict__ cb) {
    __shared__ float As[16][68];
    __shared__ float Bs[16][68];
    int m0 = blockIdx.x * 64;
    int kbase0 = blockIdx.y * 512;
    int tid = threadIdx.x;
    int tx = tid & 15, ty = tid >> 4;

    float best[4] = {3.4e38f, 3.4e38f, 3.4e38f, 3.4e38f};
    int bestk[4] = {0, 0, 0, 0};

    for (int kt = 0; kt < 8; kt++) {
        int k0 = kbase0 + kt * 64;
        float acc[4][4] = {};
        for (int p0 = 0; p0 < D_DIM; p0 += 16) {
#pragma unroll
            for (int r = 0; r < 4; r++) {
                int idx = tid + r * 256;
                int pt = idx & 15, mi = idx >> 4;
                int m = m0 + mi; if (m >= M_TOT) m = M_TOT - 1;
                int p = p0 + pt;
                As[pt][mi] = g_h2[m * D_DIM + p] * g_scale2[p] + g_shift2[p];
            }
#pragma unroll
            for (int r = 0; r < 4; r++) {
                int idx = tid + r * 256;
                int pt = idx & 15, ki = idx >> 4;
                Bs[pt][ki] = cb[(k0 + ki) * D_DIM + p0 + pt];
            }
            __syncthreads();
#pragma unroll
            for (int kk = 0; kk < 16; kk++) {
                float4 a4 = *(const float4*)&As[kk][ty * 4];
                float4 b4 = *(const float4*)&Bs[kk][tx * 4];
                float av[4] = {a4.x, a4.y, a4.z, a4.w};
                float bv[4] = {b4.x, b4.y, b4.z, b4.w};
#pragma unroll
                for (int i = 0; i < 4; i++)
#pragma unroll
                    for (int j = 0; j < 4; j++) acc[i][j] += av[i] * bv[j];
            }
            __syncthreads();
        }
#pragma unroll
        for (int i = 0; i < 4; i++) {
#pragma unroll
            for (int j = 0; j < 4; j++) {
                int k = k0 + tx * 4 + j;
                float score = g_e2[k] - 2.f * acc[i][j];
                if (score < best[i]) { best[i] = score; bestk[i] = k; }
            }
        }
    }

    /* per-m reduction across the 16 tx lanes, then global atomicMin */
    __shared__ unsigned long long kred[64][17];
#pragma unroll
    for (int i = 0; i < 4; i++) {
        unsigned u = __float_as_uint(best[i]);
        u = (u & 0x80000000u) ? ~u : (u | 0x80000000u);   /* order-preserving */
        kred[ty * 4 + i][tx] = ((unsigned long long)u << 32) | (unsigned)bestk[i];
    }
    __syncthreads();
    if (tid < 64) {
        unsigned long long mn = kred[tid][0];
#pragma unroll
        for (int t = 1; t < 16; t++) {
            unsigned long long v = kred[tid][t];
            if (v < mn) mn = v;
        }
        int m = m0 + tid;
        if (m < M_TOT) atomicMin(&g_keys[m], mn);
    }
}

/* ---------------- gather q = codebook[id], write [B,D,L'], ids, and loss ---------------- */
__global__ void gather_kernel(const float* __restrict__ cb, float* __restrict__ out) {
    int b = blockIdx.y;
    int l = blockIdx.x * 32 + threadIdx.x;
    int dt = threadIdx.y;          /* 0..7 */
    float local = 0.f;
    if (l < L_OUT) {
        int m = b * L_OUT + l;
        int id = (int)(unsigned)(g_keys[m] & 0xFFFFFFFFULL);
        if (dt == 0) out[Q_ELEMS + m] = (float)id;
        for (int d = dt; d < D_DIM; d += 8) {
            float q = cb[id * D_DIM + d];
            float z = g_h2[m * D_DIM + d] * g_scale2[d] + g_shift2[d];
            out[b * (D_DIM * L_OUT) + d * L_OUT + l] = q;
            float diff = z - q;
            local += diff * diff;
        }
    }
    __shared__ double red[256];
    int t = threadIdx.y * 32 + threadIdx.x;
    red[t] = (double)local;
    __syncthreads();
    for (int off = 128; off; off >>= 1) {
        if (t < off) red[t] += red[t + off];
        __syncthreads();
    }
    if (t == 0) atomicAdd(&g_loss, red[0]);
}

__global__ void finalize_kernel(float* __restrict__ out) {
    if (threadIdx.x == 0 && blockIdx.x == 0) {
        float loss = (float)(g_loss / (double)Q_ELEMS);
        out[Q_ELEMS + M_TOT]     = loss;   /* commitment  */
        out[Q_ELEMS + M_TOT + 1] = loss;   /* codebook_loss (identical) */
    }
}

/* ---------------- launch ---------------- */
extern "C" void kernel_launch(void* const* d_in, const int* in_sizes, int n_in,
                              void* d_out, int out_size) {
    const float* x   = (const float*)d_in[0];
    const float* w1  = (const float*)d_in[1];
    const float* b1  = (const float*)d_in[2];
    const float* g1  = (const float*)d_in[3];
    const float* be1 = (const float*)d_in[4];
    const float* w2  = (const float*)d_in[5];
    const float* b2  = (const float*)d_in[6];
    const float* g2  = (const float*)d_in[7];
    const float* be2 = (const float*)d_in[8];
    const float* cb  = (const float*)d_in[9];
    float* out = (float*)d_out;

    init_kernel<<<64, 256>>>();
    conv1_kernel<<<dim3(256, 16), 256>>>(x, w1, b1);
    bn_stage1<<<dim3(64, 8), 128>>>(0);
    bn_stage2<<<4, 256>>>(g1, be1, 0);
    conv2_kernel<<<dim3(256, 16), 256>>>(w2, b2);
    bn_stage1<<<dim3(64, 8), 128>>>(1);
    bn_stage2<<<4, 256>>>(g2, be2, 1);
    e2_kernel<<<K_CB, 128>>>(cb);
    vq_kernel<<<dim3(256, 4), 256>>>(cb);
    gather_kernel<<<dim3(16, B_SZ), dim3(32, 8)>>>(cb, out);
    finalize_kernel<<<1, 32>>>(out);
}